// round 15
// baseline (speedup 1.0000x reference)
#include <cuda_runtime.h>
#include <cuda_bf16.h>
#include <math.h>

#define NN 100000
#define NE 1600000
#define DD 128
#define NBLK 98          // ceil(NN / 1024) scan blocks per layer

typedef __nv_bfloat16 bf16;
typedef __nv_bfloat162 bf162;

// Scratch (device globals — no allocation allowed)
__device__ __align__(16) float g_agg[(size_t)NN * DD];
__device__ __align__(16) float g_x1[(size_t)NN * DD];
__device__ __align__(16) float g_p1[(size_t)NN * DD];   // x @ Wr^T + b partial
__device__ __align__(16) bf16 g_wh[4 * DD * DD];   // weights hi (Wl0,Wr0,Wl1,Wr1)
__device__ __align__(16) bf16 g_wl[4 * DD * DD];   // weights lo
__device__ int g_cnt[2 * NN];
__device__ int g_rp2[2 * NN];
__device__ int g_rowptr[2 * (NN + 1)];
__device__ int g_csr[2 * NE];
__device__ int g_bsum[2 * NBLK];

// ---------------------------------------------------------------------------
// smem geometry: bf16 tiles padded to 136 elems (272B) per row.
// A tile = 256 rows, B tile = 128 rows.
// ---------------------------------------------------------------------------
#define SA 136
#define ATILEB (256 * SA * 2)           // 69632 B
#define BTILEB (128 * SA * 2)           // 34816 B
#define OFF_AHI 0
#define OFF_ALO (OFF_AHI + ATILEB)
#define OFF_BHI (OFF_ALO + ATILEB)
#define OFF_BLO (OFF_BHI + BTILEB)
#define OFF_BIAS (OFF_BLO + BTILEB)
#define SM_TOTAL (OFF_BIAS + 512)       // ~209.4 KB

__device__ __forceinline__ unsigned smem_u32(const void* p) {
    unsigned a;
    asm("{ .reg .u64 t; cvta.to.shared.u64 t, %1; cvt.u32.u64 %0, t; }"
        : "=r"(a) : "l"(p));
    return a;
}
__device__ __forceinline__ void ldsm4(unsigned* d, unsigned addr) {
    asm volatile("ldmatrix.sync.aligned.m8n8.x4.shared.b16 {%0,%1,%2,%3}, [%4];"
                 : "=r"(d[0]), "=r"(d[1]), "=r"(d[2]), "=r"(d[3]) : "r"(addr));
}
__device__ __forceinline__ void mma16816(float* c, const unsigned* a,
                                         const unsigned* b) {
    asm volatile("mma.sync.aligned.m16n8k16.row.col.f32.bf16.bf16.f32 "
                 "{%0,%1,%2,%3}, {%4,%5,%6,%7}, {%8,%9}, {%0,%1,%2,%3};"
                 : "+f"(c[0]), "+f"(c[1]), "+f"(c[2]), "+f"(c[3])
                 : "r"(a[0]), "r"(a[1]), "r"(a[2]), "r"(a[3]),
                   "r"(b[0]), "r"(b[1]));
}
__device__ __forceinline__ void split2(float a, float b, unsigned& h, unsigned& l) {
    bf162 h2 = __floats2bfloat162_rn(a, b);
    float2 hf = __bfloat1622float2(h2);
    bf162 l2 = __floats2bfloat162_rn(a - hf.x, b - hf.y);
    h = *(unsigned*)&h2;
    l = *(unsigned*)&l2;
}

// ---------------------------------------------------------------------------
// Precompute hi/lo bf16 for all four weight matrices (4 * 4096 float4 chunks)
// ---------------------------------------------------------------------------
__global__ void conv_w4(const float* __restrict__ w0, const float* __restrict__ w1,
                        const float* __restrict__ w2, const float* __restrict__ w3,
                        bf16* __restrict__ h, bf16* __restrict__ l)
{
    int t = blockIdx.x * blockDim.x + threadIdx.x;
    if (t >= 4 * 4096) return;
    int m = t >> 12, idx = t & 4095;
    const float* src = (m == 0) ? w0 : (m == 1) ? w1 : (m == 2) ? w2 : w3;
    float4 v = *(const float4*)(src + (size_t)idx * 4);
    unsigned h0, l0, h1, l1;
    split2(v.x, v.y, h0, l0);
    split2(v.z, v.w, h1, l1);
    *(uint2*)(h + (size_t)t * 4) = make_uint2(h0, h1);
    *(uint2*)(l + (size_t)t * 4) = make_uint2(l0, l1);
}

// ---------------------------------------------------------------------------
// CSR build for BOTH layers: count -> scanA -> scanC2 (scanB folded) -> fill
// ---------------------------------------------------------------------------
__global__ void count_both(const int* __restrict__ ei0, const int* __restrict__ ei1,
                           int E0, int E1, int* __restrict__ cnt)
{
    int t = blockIdx.x * blockDim.x + threadIdx.x;
    if (t < E0) atomicAdd(cnt + ei0[E0 + t], 1);
    else if (t < E0 + E1) atomicAdd(cnt + NN + ei1[E1 + (t - E0)], 1);
}

__global__ void scanA(const int* __restrict__ cnt, int* __restrict__ bsum, int n)
{
    __shared__ int red[256];
    const int L = blockIdx.x / NBLK;
    const int b = blockIdx.x % NBLK;
    const int* c = cnt + L * NN;
    const int t = threadIdx.x;
    int base = b * 1024 + t * 4;
    int s = 0;
    #pragma unroll
    for (int j = 0; j < 4; j++)
        if (base + j < n) s += c[base + j];
    red[t] = s;
    __syncthreads();
    #pragma unroll
    for (int off = 128; off > 0; off >>= 1) {
        if (t < off) red[t] += red[t + off];
        __syncthreads();
    }
    if (t == 0) bsum[blockIdx.x] = red[0];
}

// scanC with scanB folded: each block re-scans the block sums in smem.
__global__ void scanC2(const int* __restrict__ cnt, const int* __restrict__ bsum,
                       int* __restrict__ rowptr_all, int* __restrict__ rp2_all,
                       int n)
{
    __shared__ int tsum[256];
    __shared__ int sb[2 * NBLK];
    const int t = threadIdx.x;
    if (t < 2 * NBLK) sb[t] = bsum[t];
    __syncthreads();
    if (t < 2) {
        int off = 0;
        for (int i = 0; i < NBLK; i++) {
            int v = sb[t * NBLK + i];
            sb[t * NBLK + i] = off;
            off += v;
        }
    }
    __syncthreads();

    const int L = blockIdx.x / NBLK;
    const int b = blockIdx.x % NBLK;
    const int* c = cnt + L * NN;
    int* rowptr = rowptr_all + L * (NN + 1);
    int* rp2 = rp2_all + L * NN;
    int base = b * 1024 + t * 4;
    int v[4];
    int s = 0;
    #pragma unroll
    for (int j = 0; j < 4; j++) {
        v[j] = (base + j < n) ? c[base + j] : 0;
        s += v[j];
    }
    tsum[t] = s;
    __syncthreads();
    #pragma unroll
    for (int off = 1; off < 256; off <<= 1) {
        int u = (t >= off) ? tsum[t - off] : 0;
        __syncthreads();
        tsum[t] += u;
        __syncthreads();
    }
    int excl = tsum[t] - s + sb[blockIdx.x];
    #pragma unroll
    for (int j = 0; j < 4; j++) {
        if (base + j < n) {
            rowptr[base + j] = excl;
            rp2[base + j] = excl;
            excl += v[j];
        }
    }
    if (b == NBLK - 1 && t == 255) rowptr[n] = excl;
}

__global__ void fill_both(const int* __restrict__ ei0, const int* __restrict__ ei1,
                          int E0, int E1, int* __restrict__ rp2,
                          int* __restrict__ csr)
{
    int t = blockIdx.x * blockDim.x + threadIdx.x;
    if (t < E0) {
        int src = ei0[t];
        int dst = ei0[E0 + t];
        int pos = atomicAdd(rp2 + dst, 1);
        csr[pos] = src;
    } else if (t < E0 + E1) {
        t -= E0;
        int src = ei1[t];
        int dst = ei1[E1 + t];
        int pos = atomicAdd(rp2 + NN + dst, 1);
        csr[NE + pos] = src;
    }
}

// ---------------------------------------------------------------------------
// Gather: one warp per destination node; mean of neighbor rows, no atomics.
// fp32 reads, unroll-4, regs=32 (latency hidden by occupancy).
// ---------------------------------------------------------------------------
__global__ void gather_kernel(const float* __restrict__ x,
                              const int* __restrict__ rowptr,
                              const int* __restrict__ csr,
                              float* __restrict__ agg, int n)
{
    int w = (blockIdx.x * blockDim.x + threadIdx.x) >> 5;
    if (w >= n) return;
    const int lane = threadIdx.x & 31;
    const int beg = rowptr[w];
    const int end = rowptr[w + 1];

    float4 acc = make_float4(0.f, 0.f, 0.f, 0.f);
    int i = beg;
    for (; i + 4 <= end; i += 4) {
        int s0 = __ldg(csr + i);
        int s1 = __ldg(csr + i + 1);
        int s2 = __ldg(csr + i + 2);
        int s3 = __ldg(csr + i + 3);
        float4 v0 = *(const float4*)(x + (size_t)s0 * DD + lane * 4);
        float4 v1 = *(const float4*)(x + (size_t)s1 * DD + lane * 4);
        float4 v2 = *(const float4*)(x + (size_t)s2 * DD + lane * 4);
        float4 v3 = *(const float4*)(x + (size_t)s3 * DD + lane * 4);
        acc.x += v0.x + v1.x + v2.x + v3.x;
        acc.y += v0.y + v1.y + v2.y + v3.y;
        acc.z += v0.z + v1.z + v2.z + v3.z;
        acc.w += v0.w + v1.w + v2.w + v3.w;
    }
    for (; i < end; i++) {
        int s = __ldg(csr + i);
        float4 v = *(const float4*)(x + (size_t)s * DD + lane * 4);
        acc.x += v.x; acc.y += v.y; acc.z += v.z; acc.w += v.w;
    }
    float inv = 1.0f / fmaxf((float)(end - beg), 1.0f);
    acc.x *= inv; acc.y *= inv; acc.z *= inv; acc.w *= inv;
    *(float4*)(agg + (size_t)w * DD + lane * 4) = acc;
}

// ---------------------------------------------------------------------------
// Convert 256x128 fp32 (row-guarded) into bf16 hi/lo tiles in smem.
// 512 threads: row = tid>>1 (0..255), col half = (tid&1)*64.
// ---------------------------------------------------------------------------
__device__ __forceinline__ void conv_a(const float* __restrict__ src,
                                       int row0, int nvalid, char* sm, int tid)
{
    const int row = tid >> 1;
    const int c0 = (tid & 1) * 64;
    const bool valid = (row0 + row) < nvalid;
    const float* p = src + (size_t)(row0 + row) * DD + c0;
    char* ph = sm + OFF_AHI + (row * SA + c0) * 2;
    char* pl = sm + OFF_ALO + (row * SA + c0) * 2;
    #pragma unroll
    for (int c = 0; c < 64; c += 8) {
        float4 f0 = make_float4(0.f, 0.f, 0.f, 0.f);
        float4 f1 = make_float4(0.f, 0.f, 0.f, 0.f);
        if (valid) {
            f0 = *(const float4*)(p + c);
            f1 = *(const float4*)(p + c + 4);
        }
        float xs[8] = {f0.x, f0.y, f0.z, f0.w, f1.x, f1.y, f1.z, f1.w};
        unsigned hw[4], lw[4];
        #pragma unroll
        for (int j = 0; j < 4; j++)
            split2(xs[2 * j], xs[2 * j + 1], hw[j], lw[j]);
        *(uint4*)(ph + c * 2) = make_uint4(hw[0], hw[1], hw[2], hw[3]);
        *(uint4*)(pl + c * 2) = make_uint4(lw[0], lw[1], lw[2], lw[3]);
    }
}

// Copy one [128 x 128] bf16 weight tile from global into padded smem.
__device__ __forceinline__ void copy_b(const bf16* __restrict__ src,
                                       char* sm, int off, int tid)
{
    #pragma unroll
    for (int j = 0; j < 4; j++) {
        int c = tid + j * 512;          // 0..2047
        int r = c >> 4;
        int ce = (c & 15) * 8;          // col element
        uint4 v = *(const uint4*)(src + (size_t)r * DD + ce);
        *(uint4*)(sm + off + (r * SA + ce) * 2) = v;
    }
}

// ---------------------------------------------------------------------------
// Half-GEMM on tensor cores (mma.sync bf16, hi/lo split, fp32 accum):
// acc = A @ W^T. 256x128 tile per CTA, 512 threads = 16 warps, warp 32x64.
// mode 0: out = acc + bias              (gemmA: P1 = x@Wr + b)
// mode 1: out = acc + p1                (gemmB last layer)
// mode 2: out = gelu(acc + p1)          (gemmB layer 0)
// ---------------------------------------------------------------------------
__global__ void __launch_bounds__(512, 1) gemm_half(
    const float* __restrict__ A,
    const bf16* __restrict__ wh_, const bf16* __restrict__ wl_,
    const float* __restrict__ bias,
    const float* __restrict__ p1,
    float* __restrict__ out,
    int n_nodes, int mode)
{
    extern __shared__ char sm[];
    const int tid = threadIdx.x;
    const int wid = tid >> 5;
    const int lane = tid & 31;
    const int row0 = blockIdx.x * 256;
    const int wm = (wid & 7) * 32;      // warp row base (0..224)
    const int wn = (wid >> 3) * 64;     // warp col base
    float* sbias = (float*)(sm + OFF_BIAS);

    if (mode == 0 && tid < 128) sbias[tid] = bias[tid];

    float acc[2][8][4];
    #pragma unroll
    for (int mt = 0; mt < 2; mt++)
        #pragma unroll
        for (int nt = 0; nt < 8; nt++)
            #pragma unroll
            for (int c = 0; c < 4; c++) acc[mt][nt][c] = 0.0f;

    const unsigned sbase = smem_u32(sm);
    const int lr = lane & 7;
    const int mat = lane >> 3;
    const unsigned a_row = wm + lr + ((mat & 1) << 3);
    const unsigned a_co  = ((mat >> 1) << 3);
    const unsigned b_row = wn + lr + ((mat >> 1) << 3);
    const unsigned b_co  = ((mat & 1) << 3);
    const unsigned a_base = sbase + (a_row * SA + a_co) * 2;
    const unsigned b_base = sbase + (b_row * SA + b_co) * 2;

    conv_a(A, row0, n_nodes, sm, tid);
    copy_b(wh_, sm, OFF_BHI, tid);
    copy_b(wl_, sm, OFF_BLO, tid);
    __syncthreads();

    #pragma unroll 1
    for (int ks = 0; ks < 8; ks++) {
        const unsigned kb = ks * 32;   // 16 bf16 = 32 bytes
        unsigned ahi[2][4], alo[2][4];
        #pragma unroll
        for (int mt = 0; mt < 2; mt++) {
            unsigned off = mt * (16 * SA * 2) + kb;
            ldsm4(ahi[mt], a_base + OFF_AHI + off);
            ldsm4(alo[mt], a_base + OFF_ALO + off);
        }
        unsigned bhi[4][4], blo[4][4];
        #pragma unroll
        for (int np = 0; np < 4; np++) {
            unsigned off = np * (16 * SA * 2) + kb;
            ldsm4(bhi[np], b_base + OFF_BHI + off);
            ldsm4(blo[np], b_base + OFF_BLO + off);
        }
        #pragma unroll
        for (int mt = 0; mt < 2; mt++)
            #pragma unroll
            for (int nt = 0; nt < 8; nt++) {
                const unsigned* bh = &bhi[nt >> 1][(nt & 1) * 2];
                const unsigned* bl = &blo[nt >> 1][(nt & 1) * 2];
                mma16816(acc[mt][nt], ahi[mt], bh);
                mma16816(acc[mt][nt], ahi[mt], bl);
                mma16816(acc[mt][nt], alo[mt], bh);
            }
    }

    // Epilogue: c frag (r = lane>>2, c = 2*(lane&3)): {c0,c1}@r, {c2,c3}@r+8
    const int cr = lane >> 2;
    const int cc = 2 * (lane & 3);
    #pragma unroll
    for (int mt = 0; mt < 2; mt++) {
        int r_lo = row0 + wm + mt * 16 + cr;
        int r_hi = r_lo + 8;
        #pragma unroll
        for (int nt = 0; nt < 8; nt++) {
            int col = wn + nt * 8 + cc;
            float a0 = 0.f, a1 = 0.f, a2 = 0.f, a3 = 0.f;
            if (mode == 0) {
                a0 = a2 = sbias[col];
                a1 = a3 = sbias[col + 1];
            } else {
                if (r_lo < n_nodes) {
                    float2 q = *(const float2*)(p1 + (size_t)r_lo * DD + col);
                    a0 = q.x; a1 = q.y;
                }
                if (r_hi < n_nodes) {
                    float2 q = *(const float2*)(p1 + (size_t)r_hi * DD + col);
                    a2 = q.x; a3 = q.y;
                }
            }
            float v0 = acc[mt][nt][0] + a0;
            float v1 = acc[mt][nt][1] + a1;
            float v2 = acc[mt][nt][2] + a2;
            float v3 = acc[mt][nt][3] + a3;
            if (mode == 2) {
                v0 = 0.5f * v0 * (1.0f + erff(v0 * 0.70710678118654752f));
                v1 = 0.5f * v1 * (1.0f + erff(v1 * 0.70710678118654752f));
                v2 = 0.5f * v2 * (1.0f + erff(v2 * 0.70710678118654752f));
                v3 = 0.5f * v3 * (1.0f + erff(v3 * 0.70710678118654752f));
            }
            if (r_lo < n_nodes)
                *(float2*)(out + (size_t)r_lo * DD + col) = make_float2(v0, v1);
            if (r_hi < n_nodes)
                *(float2*)(out + (size_t)r_hi * DD + col) = make_float2(v2, v3);
        }
    }
}

// ---------------------------------------------------------------------------
extern "C" void kernel_launch(void* const* d_in, const int* in_sizes, int n_in,
                              void* d_out, int out_size)
{
    const float* embs = (const float*)d_in[0];
    const int*   ei0  = (const int*)d_in[1];
    const int*   ei1  = (const int*)d_in[2];
    const float* wl0  = (const float*)d_in[3];
    const float* wr0  = (const float*)d_in[4];
    const float* b0   = (const float*)d_in[5];
    const float* wl1  = (const float*)d_in[6];
    const float* wr1  = (const float*)d_in[7];
    const float* b1   = (const float*)d_in[8];
    float* out = (float*)d_out;

    const int N  = in_sizes[0] / DD;
    const int E0 = in_sizes[1] / 2;
    const int E1 = in_sizes[2] / 2;

    float *dagg, *dx1, *dp1;
    bf16 *dwh, *dwl;
    int *dcnt, *drp2, *drp, *dcsr, *dbsum;
    cudaGetSymbolAddress((void**)&dagg, g_agg);
    cudaGetSymbolAddress((void**)&dx1,  g_x1);
    cudaGetSymbolAddress((void**)&dp1,  g_p1);
    cudaGetSymbolAddress((void**)&dwh,  g_wh);
    cudaGetSymbolAddress((void**)&dwl,  g_wl);
    cudaGetSymbolAddress((void**)&dcnt, g_cnt);
    cudaGetSymbolAddress((void**)&drp2, g_rp2);
    cudaGetSymbolAddress((void**)&drp,  g_rowptr);
    cudaGetSymbolAddress((void**)&dcsr, g_csr);
    cudaGetSymbolAddress((void**)&dbsum, g_bsum);

    cudaFuncSetAttribute(gemm_half,
                         cudaFuncAttributeMaxDynamicSharedMemorySize, SM_TOTAL);

    // Side stream + events, created once on the first (non-capture) call.
    // The launch sequence below is IDENTICAL on every call.
    static cudaStream_t s1 = nullptr;
    static cudaEvent_t evF = nullptr, ev1 = nullptr, ev2 = nullptr, ev3 = nullptr;
    static bool have_side = false;
    static bool tried = false;
    if (!tried) {
        tried = true;
        have_side =
            cudaStreamCreateWithFlags(&s1, cudaStreamNonBlocking) == cudaSuccess &&
            cudaEventCreateWithFlags(&evF, cudaEventDisableTiming) == cudaSuccess &&
            cudaEventCreateWithFlags(&ev1, cudaEventDisableTiming) == cudaSuccess &&
            cudaEventCreateWithFlags(&ev2, cudaEventDisableTiming) == cudaSuccess &&
            cudaEventCreateWithFlags(&ev3, cudaEventDisableTiming) == cudaSuccess;
    }

    const int gemm_blocks = (N + 255) / 256;
    const int gather_blocks = (N * 32 + 255) / 256;
    const int EB = E0 + E1;
    const cudaStream_t s0 = (cudaStream_t)0;

    if (have_side) {
        // ---- fork s1 from the capture stream (legal capture pattern) ----
        cudaEventRecord(evF, s0);
        cudaStreamWaitEvent(s1, evF, 0);

        // ---- s1: weights + gemmA0 (concurrent with CSR + gather0) ----
        conv_w4<<<(4 * 4096 + 255) / 256, 256, 0, s1>>>(wl0, wr0, wl1, wr1,
                                                        dwh, dwl);
        gemm_half<<<gemm_blocks, 512, SM_TOTAL, s1>>>(embs,
            dwh + DD * DD, dwl + DD * DD,      // Wr0
            b0, nullptr, dp1, N, 0);
        cudaEventRecord(ev1, s1);

        // ---- s0: CSR build for both layers + gather0 ----
        cudaMemsetAsync(dcnt, 0, 2 * NN * sizeof(int), s0);
        count_both<<<(EB + 255) / 256, 256, 0, s0>>>(ei0, ei1, E0, E1, dcnt);
        scanA<<<2 * NBLK, 256, 0, s0>>>(dcnt, dbsum, N);
        scanC2<<<2 * NBLK, 256, 0, s0>>>(dcnt, dbsum, drp, drp2, N);
        fill_both<<<(EB + 255) / 256, 256, 0, s0>>>(ei0, ei1, E0, E1, drp2, dcsr);
        gather_kernel<<<gather_blocks, 256, 0, s0>>>(embs, drp, dcsr, dagg, N);

        // ---- join gemmA0, run gemmB0 ----
        cudaStreamWaitEvent(s0, ev1, 0);
        gemm_half<<<gemm_blocks, 512, SM_TOTAL, s0>>>(dagg,
            dwh, dwl,                          // Wl0
            nullptr, dp1, dx1, N, 2);
        cudaEventRecord(ev2, s0);

        // ---- s1: gemmA1 (concurrent with gather1) ----
        cudaStreamWaitEvent(s1, ev2, 0);
        gemm_half<<<gemm_blocks, 512, SM_TOTAL, s1>>>(dx1,
            dwh + 3 * DD * DD, dwl + 3 * DD * DD,  // Wr1
            b1, nullptr, dp1, N, 0);
        cudaEventRecord(ev3, s1);

        // ---- s0: gather1, join gemmA1, gemmB1 ----
        gather_kernel<<<gather_blocks, 256, 0, s0>>>(dx1, drp + (NN + 1),
                                                     dcsr + NE, dagg, N);
        cudaStreamWaitEvent(s0, ev3, 0);
        gemm_half<<<gemm_blocks, 512, SM_TOTAL, s0>>>(dagg,
            dwh + 2 * DD * DD, dwl + 2 * DD * DD,  // Wl1
            nullptr, dp1, out, N, 1);
    } else {
        // ---- serial fallback (same kernels, null stream) ----
        cudaMemsetAsync(dcnt, 0, 2 * NN * sizeof(int));
        count_both<<<(EB + 255) / 256, 256>>>(ei0, ei1, E0, E1, dcnt);
        conv_w4<<<(4 * 4096 + 255) / 256, 256>>>(wl0, wr0, wl1, wr1, dwh, dwl);
        scanA<<<2 * NBLK, 256>>>(dcnt, dbsum, N);
        scanC2<<<2 * NBLK, 256>>>(dcnt, dbsum, drp, drp2, N);
        fill_both<<<(EB + 255) / 256, 256>>>(ei0, ei1, E0, E1, drp2, dcsr);

        gemm_half<<<gemm_blocks, 512, SM_TOTAL>>>(embs,
            dwh + DD * DD, dwl + DD * DD, b0, nullptr, dp1, N, 0);
        gather_kernel<<<gather_blocks, 256>>>(embs, drp, dcsr, dagg, N);
        gemm_half<<<gemm_blocks, 512, SM_TOTAL>>>(dagg,
            dwh, dwl, nullptr, dp1, dx1, N, 2);

        gemm_half<<<gemm_blocks, 512, SM_TOTAL>>>(dx1,
            dwh + 3 * DD * DD, dwl + 3 * DD * DD, b1, nullptr, dp1, N, 0);
        gather_kernel<<<gather_blocks, 256>>>(dx1, drp + (NN + 1), dcsr + NE,
                                              dagg, N);
        gemm_half<<<gemm_blocks, 512, SM_TOTAL>>>(dagg,
            dwh + 2 * DD * DD, dwl + 2 * DD * DD, nullptr, dp1, out, N, 1);
    }
}

// round 17
// speedup vs baseline: 1.1370x; 1.1370x over previous
#include <cuda_runtime.h>
#include <cuda_bf16.h>
#include <math.h>

#define NN 100000
#define NE 1600000
#define DD 128
#define NBLK 98          // ceil(NN / 1024) scan blocks per layer

typedef __nv_bfloat16 bf16;
typedef __nv_bfloat162 bf162;

// Scratch (device globals — no allocation allowed)
__device__ __align__(16) float g_agg[(size_t)NN * DD];
__device__ __align__(16) float g_x1[(size_t)NN * DD];
__device__ __align__(16) bf16 g_wh[4 * DD * DD];   // weights hi (Wl0,Wr0,Wl1,Wr1)
__device__ __align__(16) bf16 g_wl[4 * DD * DD];   // weights lo
__device__ int g_cnt[2 * NN];
__device__ int g_rp2[2 * NN];
__device__ int g_rowptr[2 * (NN + 1)];
__device__ int g_csr[2 * NE];
__device__ int g_bsum[2 * NBLK];

// ---------------------------------------------------------------------------
// smem geometry: bf16 tiles padded to 136 elems (272B) per row.
// A tile = 256 rows, B tile = 128 rows.
// ---------------------------------------------------------------------------
#define SA 136
#define ATILEB (256 * SA * 2)           // 69632 B
#define BTILEB (128 * SA * 2)           // 34816 B
#define OFF_AHI 0
#define OFF_ALO (OFF_AHI + ATILEB)
#define OFF_BHI (OFF_ALO + ATILEB)
#define OFF_BLO (OFF_BHI + BTILEB)
#define OFF_BIAS (OFF_BLO + BTILEB)
#define SM_TOTAL (OFF_BIAS + 512)       // ~209.4 KB

__device__ __forceinline__ unsigned smem_u32(const void* p) {
    unsigned a;
    asm("{ .reg .u64 t; cvta.to.shared.u64 t, %1; cvt.u32.u64 %0, t; }"
        : "=r"(a) : "l"(p));
    return a;
}
__device__ __forceinline__ void ldsm4(unsigned* d, unsigned addr) {
    asm volatile("ldmatrix.sync.aligned.m8n8.x4.shared.b16 {%0,%1,%2,%3}, [%4];"
                 : "=r"(d[0]), "=r"(d[1]), "=r"(d[2]), "=r"(d[3]) : "r"(addr));
}
__device__ __forceinline__ void mma16816(float* c, const unsigned* a,
                                         const unsigned* b) {
    asm volatile("mma.sync.aligned.m16n8k16.row.col.f32.bf16.bf16.f32 "
                 "{%0,%1,%2,%3}, {%4,%5,%6,%7}, {%8,%9}, {%0,%1,%2,%3};"
                 : "+f"(c[0]), "+f"(c[1]), "+f"(c[2]), "+f"(c[3])
                 : "r"(a[0]), "r"(a[1]), "r"(a[2]), "r"(a[3]),
                   "r"(b[0]), "r"(b[1]));
}
__device__ __forceinline__ void split2(float a, float b, unsigned& h, unsigned& l) {
    bf162 h2 = __floats2bfloat162_rn(a, b);
    float2 hf = __bfloat1622float2(h2);
    bf162 l2 = __floats2bfloat162_rn(a - hf.x, b - hf.y);
    h = *(unsigned*)&h2;
    l = *(unsigned*)&l2;
}

// ---------------------------------------------------------------------------
// Precompute hi/lo bf16 for all four weight matrices (4 * 4096 float4 chunks)
// ---------------------------------------------------------------------------
__global__ void conv_w4(const float* __restrict__ w0, const float* __restrict__ w1,
                        const float* __restrict__ w2, const float* __restrict__ w3,
                        bf16* __restrict__ h, bf16* __restrict__ l)
{
    int t = blockIdx.x * blockDim.x + threadIdx.x;
    if (t >= 4 * 4096) return;
    int m = t >> 12, idx = t & 4095;
    const float* src = (m == 0) ? w0 : (m == 1) ? w1 : (m == 2) ? w2 : w3;
    float4 v = *(const float4*)(src + (size_t)idx * 4);
    unsigned h0, l0, h1, l1;
    split2(v.x, v.y, h0, l0);
    split2(v.z, v.w, h1, l1);
    *(uint2*)(h + (size_t)t * 4) = make_uint2(h0, h1);
    *(uint2*)(l + (size_t)t * 4) = make_uint2(l0, l1);
}

// ---------------------------------------------------------------------------
// Per-layer CSR build: count -> scanA1 -> scanC1 (block-sum scan folded) -> fill
// ---------------------------------------------------------------------------
__global__ void count_one(const int* __restrict__ ei, int E, int* __restrict__ cnt)
{
    int t = blockIdx.x * blockDim.x + threadIdx.x;
    if (t < E) atomicAdd(cnt + ei[E + t], 1);
}

__global__ void scanA1(const int* __restrict__ cnt, int* __restrict__ bsum, int n)
{
    __shared__ int red[256];
    const int b = blockIdx.x;
    const int t = threadIdx.x;
    int base = b * 1024 + t * 4;
    int s = 0;
    #pragma unroll
    for (int j = 0; j < 4; j++)
        if (base + j < n) s += cnt[base + j];
    red[t] = s;
    __syncthreads();
    #pragma unroll
    for (int off = 128; off > 0; off >>= 1) {
        if (t < off) red[t] += red[t + off];
        __syncthreads();
    }
    if (t == 0) bsum[b] = red[0];
}

// scanC1: per-layer; each block re-scans the NBLK block sums in smem.
__global__ void scanC1(const int* __restrict__ cnt, const int* __restrict__ bsum,
                       int* __restrict__ rowptr, int* __restrict__ rp2, int n)
{
    __shared__ int tsum[256];
    __shared__ int sb[NBLK];
    const int t = threadIdx.x;
    if (t < NBLK) sb[t] = bsum[t];
    __syncthreads();
    if (t == 0) {
        int off = 0;
        for (int i = 0; i < NBLK; i++) {
            int v = sb[i];
            sb[i] = off;
            off += v;
        }
    }
    __syncthreads();

    const int b = blockIdx.x;
    int base = b * 1024 + t * 4;
    int v[4];
    int s = 0;
    #pragma unroll
    for (int j = 0; j < 4; j++) {
        v[j] = (base + j < n) ? cnt[base + j] : 0;
        s += v[j];
    }
    tsum[t] = s;
    __syncthreads();
    #pragma unroll
    for (int off = 1; off < 256; off <<= 1) {
        int u = (t >= off) ? tsum[t - off] : 0;
        __syncthreads();
        tsum[t] += u;
        __syncthreads();
    }
    int excl = tsum[t] - s + sb[b];
    #pragma unroll
    for (int j = 0; j < 4; j++) {
        if (base + j < n) {
            rowptr[base + j] = excl;
            rp2[base + j] = excl;
            excl += v[j];
        }
    }
    if (b == NBLK - 1 && t == 255) rowptr[n] = excl;
}

__global__ void fill_one(const int* __restrict__ ei, int E,
                         int* __restrict__ rp2, int* __restrict__ csr)
{
    int t = blockIdx.x * blockDim.x + threadIdx.x;
    if (t < E) {
        int src = ei[t];
        int dst = ei[E + t];
        int pos = atomicAdd(rp2 + dst, 1);
        csr[pos] = src;
    }
}

// ---------------------------------------------------------------------------
// Gather: one warp per destination node; mean of neighbor rows, no atomics.
// fp32 reads, unroll-4, regs=32 (latency hidden by occupancy).
// ---------------------------------------------------------------------------
__global__ void gather_kernel(const float* __restrict__ x,
                              const int* __restrict__ rowptr,
                              const int* __restrict__ csr,
                              float* __restrict__ agg, int n)
{
    int w = (blockIdx.x * blockDim.x + threadIdx.x) >> 5;
    if (w >= n) return;
    const int lane = threadIdx.x & 31;
    const int beg = rowptr[w];
    const int end = rowptr[w + 1];

    float4 acc = make_float4(0.f, 0.f, 0.f, 0.f);
    int i = beg;
    for (; i + 4 <= end; i += 4) {
        int s0 = __ldg(csr + i);
        int s1 = __ldg(csr + i + 1);
        int s2 = __ldg(csr + i + 2);
        int s3 = __ldg(csr + i + 3);
        float4 v0 = *(const float4*)(x + (size_t)s0 * DD + lane * 4);
        float4 v1 = *(const float4*)(x + (size_t)s1 * DD + lane * 4);
        float4 v2 = *(const float4*)(x + (size_t)s2 * DD + lane * 4);
        float4 v3 = *(const float4*)(x + (size_t)s3 * DD + lane * 4);
        acc.x += v0.x + v1.x + v2.x + v3.x;
        acc.y += v0.y + v1.y + v2.y + v3.y;
        acc.z += v0.z + v1.z + v2.z + v3.z;
        acc.w += v0.w + v1.w + v2.w + v3.w;
    }
    for (; i < end; i++) {
        int s = __ldg(csr + i);
        float4 v = *(const float4*)(x + (size_t)s * DD + lane * 4);
        acc.x += v.x; acc.y += v.y; acc.z += v.z; acc.w += v.w;
    }
    float inv = 1.0f / fmaxf((float)(end - beg), 1.0f);
    acc.x *= inv; acc.y *= inv; acc.z *= inv; acc.w *= inv;
    *(float4*)(agg + (size_t)w * DD + lane * 4) = acc;
}

// ---------------------------------------------------------------------------
// Convert 256x128 fp32 (row-guarded) into bf16 hi/lo tiles in smem.
// 512 threads: row = tid>>1 (0..255), col half = (tid&1)*64.
// ---------------------------------------------------------------------------
__device__ __forceinline__ void conv_a(const float* __restrict__ src,
                                       int row0, int nvalid, char* sm, int tid)
{
    const int row = tid >> 1;
    const int c0 = (tid & 1) * 64;
    const bool valid = (row0 + row) < nvalid;
    const float* p = src + (size_t)(row0 + row) * DD + c0;
    char* ph = sm + OFF_AHI + (row * SA + c0) * 2;
    char* pl = sm + OFF_ALO + (row * SA + c0) * 2;
    #pragma unroll
    for (int c = 0; c < 64; c += 8) {
        float4 f0 = make_float4(0.f, 0.f, 0.f, 0.f);
        float4 f1 = make_float4(0.f, 0.f, 0.f, 0.f);
        if (valid) {
            f0 = *(const float4*)(p + c);
            f1 = *(const float4*)(p + c + 4);
        }
        float xs[8] = {f0.x, f0.y, f0.z, f0.w, f1.x, f1.y, f1.z, f1.w};
        unsigned hw[4], lw[4];
        #pragma unroll
        for (int j = 0; j < 4; j++)
            split2(xs[2 * j], xs[2 * j + 1], hw[j], lw[j]);
        *(uint4*)(ph + c * 2) = make_uint4(hw[0], hw[1], hw[2], hw[3]);
        *(uint4*)(pl + c * 2) = make_uint4(lw[0], lw[1], lw[2], lw[3]);
    }
}

// Copy one [128 x 128] bf16 weight tile from global into padded smem.
__device__ __forceinline__ void copy_b(const bf16* __restrict__ src,
                                       char* sm, int off, int tid)
{
    #pragma unroll
    for (int j = 0; j < 4; j++) {
        int c = tid + j * 512;          // 0..2047
        int r = c >> 4;
        int ce = (c & 15) * 8;          // col element
        uint4 v = *(const uint4*)(src + (size_t)r * DD + ce);
        *(uint4*)(sm + off + (r * SA + ce) * 2) = v;
    }
}

// ---------------------------------------------------------------------------
// Fused GEMM on tensor cores (mma.sync bf16, hi/lo split, fp32 accum):
// out[i,:] = act( agg[i,:] @ Wl^T + x[i,:] @ Wr^T + b )
// 256x128 tile per CTA, 512 threads = 16 warps (8m x 2n), warp tile 32x64.
// Weights pre-split in global; A converted in-kernel from fp32.
// ---------------------------------------------------------------------------
__global__ void __launch_bounds__(512, 1) fused_tc(
    const float* __restrict__ x,
    const float* __restrict__ agg,
    const bf16* __restrict__ wlh, const bf16* __restrict__ wll,
    const bf16* __restrict__ wrh, const bf16* __restrict__ wrl,
    const float* __restrict__ bias,
    float* __restrict__ out,
    int n_nodes, int do_gelu)
{
    extern __shared__ char sm[];
    const int tid = threadIdx.x;
    const int wid = tid >> 5;
    const int lane = tid & 31;
    const int row0 = blockIdx.x * 256;
    const int wm = (wid & 7) * 32;      // warp row base (0..224)
    const int wn = (wid >> 3) * 64;     // warp col base
    float* sbias = (float*)(sm + OFF_BIAS);

    if (tid < 128) sbias[tid] = bias[tid];

    float acc[2][8][4];
    #pragma unroll
    for (int mt = 0; mt < 2; mt++)
        #pragma unroll
        for (int nt = 0; nt < 8; nt++)
            #pragma unroll
            for (int c = 0; c < 4; c++) acc[mt][nt][c] = 0.0f;

    const unsigned sbase = smem_u32(sm);
    const int lr = lane & 7;
    const int mat = lane >> 3;
    const unsigned a_row = wm + lr + ((mat & 1) << 3);
    const unsigned a_co  = ((mat >> 1) << 3);
    const unsigned b_row = wn + lr + ((mat >> 1) << 3);
    const unsigned b_co  = ((mat & 1) << 3);
    const unsigned a_base = sbase + (a_row * SA + a_co) * 2;
    const unsigned b_base = sbase + (b_row * SA + b_co) * 2;

    #pragma unroll 1
    for (int ph = 0; ph < 2; ph++) {
        __syncthreads();   // prior-phase smem reads complete
        conv_a(ph ? x : agg, row0, n_nodes, sm, tid);
        copy_b(ph ? wrh : wlh, sm, OFF_BHI, tid);
        copy_b(ph ? wrl : wll, sm, OFF_BLO, tid);
        __syncthreads();

        #pragma unroll 1
        for (int ks = 0; ks < 8; ks++) {
            const unsigned kb = ks * 32;   // 16 bf16 = 32 bytes
            unsigned ahi[2][4], alo[2][4];
            #pragma unroll
            for (int mt = 0; mt < 2; mt++) {
                unsigned off = mt * (16 * SA * 2) + kb;
                ldsm4(ahi[mt], a_base + OFF_AHI + off);
                ldsm4(alo[mt], a_base + OFF_ALO + off);
            }
            unsigned bhi[4][4], blo[4][4];
            #pragma unroll
            for (int np = 0; np < 4; np++) {
                unsigned off = np * (16 * SA * 2) + kb;
                ldsm4(bhi[np], b_base + OFF_BHI + off);
                ldsm4(blo[np], b_base + OFF_BLO + off);
            }
            #pragma unroll
            for (int mt = 0; mt < 2; mt++)
                #pragma unroll
                for (int nt = 0; nt < 8; nt++) {
                    const unsigned* bh = &bhi[nt >> 1][(nt & 1) * 2];
                    const unsigned* bl = &blo[nt >> 1][(nt & 1) * 2];
                    mma16816(acc[mt][nt], ahi[mt], bh);
                    mma16816(acc[mt][nt], ahi[mt], bl);
                    mma16816(acc[mt][nt], alo[mt], bh);
                }
        }
    }

    // Epilogue: c frag (r = lane>>2, c = 2*(lane&3)): {c0,c1}@r, {c2,c3}@r+8
    const int cr = lane >> 2;
    const int cc = 2 * (lane & 3);
    #pragma unroll
    for (int mt = 0; mt < 2; mt++) {
        int r_lo = row0 + wm + mt * 16 + cr;
        int r_hi = r_lo + 8;
        #pragma unroll
        for (int nt = 0; nt < 8; nt++) {
            int col = wn + nt * 8 + cc;
            float b0 = sbias[col], b1 = sbias[col + 1];
            float v0 = acc[mt][nt][0] + b0;
            float v1 = acc[mt][nt][1] + b1;
            float v2 = acc[mt][nt][2] + b0;
            float v3 = acc[mt][nt][3] + b1;
            if (do_gelu) {
                v0 = 0.5f * v0 * (1.0f + erff(v0 * 0.70710678118654752f));
                v1 = 0.5f * v1 * (1.0f + erff(v1 * 0.70710678118654752f));
                v2 = 0.5f * v2 * (1.0f + erff(v2 * 0.70710678118654752f));
                v3 = 0.5f * v3 * (1.0f + erff(v3 * 0.70710678118654752f));
            }
            if (r_lo < n_nodes)
                *(float2*)(out + (size_t)r_lo * DD + col) = make_float2(v0, v1);
            if (r_hi < n_nodes)
                *(float2*)(out + (size_t)r_hi * DD + col) = make_float2(v2, v3);
        }
    }
}

// ---------------------------------------------------------------------------
extern "C" void kernel_launch(void* const* d_in, const int* in_sizes, int n_in,
                              void* d_out, int out_size)
{
    const float* embs = (const float*)d_in[0];
    const int*   ei0  = (const int*)d_in[1];
    const int*   ei1  = (const int*)d_in[2];
    const float* wl0  = (const float*)d_in[3];
    const float* wr0  = (const float*)d_in[4];
    const float* b0   = (const float*)d_in[5];
    const float* wl1  = (const float*)d_in[6];
    const float* wr1  = (const float*)d_in[7];
    const float* b1   = (const float*)d_in[8];
    float* out = (float*)d_out;

    const int N  = in_sizes[0] / DD;
    const int E0 = in_sizes[1] / 2;
    const int E1 = in_sizes[2] / 2;

    float *dagg, *dx1;
    bf16 *dwh, *dwl;
    int *dcnt, *drp2, *drp, *dcsr, *dbsum;
    cudaGetSymbolAddress((void**)&dagg, g_agg);
    cudaGetSymbolAddress((void**)&dx1,  g_x1);
    cudaGetSymbolAddress((void**)&dwh,  g_wh);
    cudaGetSymbolAddress((void**)&dwl,  g_wl);
    cudaGetSymbolAddress((void**)&dcnt, g_cnt);
    cudaGetSymbolAddress((void**)&drp2, g_rp2);
    cudaGetSymbolAddress((void**)&drp,  g_rowptr);
    cudaGetSymbolAddress((void**)&dcsr, g_csr);
    cudaGetSymbolAddress((void**)&dbsum, g_bsum);

    cudaFuncSetAttribute(fused_tc,
                         cudaFuncAttributeMaxDynamicSharedMemorySize, SM_TOTAL);

    // Side stream + events, created once on the first (non-capture) call.
    // Launch sequence below is IDENTICAL on every call.
    static cudaStream_t s1 = nullptr;
    static cudaEvent_t evF = nullptr, evW = nullptr, evC = nullptr;
    static bool have_side = false;
    static bool tried = false;
    if (!tried) {
        tried = true;
        have_side =
            cudaStreamCreateWithFlags(&s1, cudaStreamNonBlocking) == cudaSuccess &&
            cudaEventCreateWithFlags(&evF, cudaEventDisableTiming) == cudaSuccess &&
            cudaEventCreateWithFlags(&evW, cudaEventDisableTiming) == cudaSuccess &&
            cudaEventCreateWithFlags(&evC, cudaEventDisableTiming) == cudaSuccess;
    }

    const int gemm_blocks = (N + 255) / 256;
    const int gather_blocks = (N * 32 + 255) / 256;
    const cudaStream_t s0 = (cudaStream_t)0;

    if (have_side) {
        // ---- fork s1 from the capture stream (proven legal pattern) ----
        cudaEventRecord(evF, s0);
        cudaStreamWaitEvent(s1, evF, 0);

        // ---- s1: weights, then the ENTIRE layer-1 CSR build ----
        conv_w4<<<(4 * 4096 + 255) / 256, 256, 0, s1>>>(wl0, wr0, wl1, wr1,
                                                        dwh, dwl);
        cudaEventRecord(evW, s1);
        cudaMemsetAsync(dcnt + NN, 0, NN * sizeof(int), s1);
        count_one<<<(E1 + 255) / 256, 256, 0, s1>>>(ei1, E1, dcnt + NN);
        scanA1<<<NBLK, 256, 0, s1>>>(dcnt + NN, dbsum + NBLK, N);
        scanC1<<<NBLK, 256, 0, s1>>>(dcnt + NN, dbsum + NBLK,
                                     drp + (NN + 1), drp2 + NN, N);
        fill_one<<<(E1 + 255) / 256, 256, 0, s1>>>(ei1, E1, drp2 + NN, dcsr + NE);
        cudaEventRecord(evC, s1);

        // ---- s0: layer-0 CSR + gather0 ----
        cudaMemsetAsync(dcnt, 0, NN * sizeof(int), s0);
        count_one<<<(E0 + 255) / 256, 256, 0, s0>>>(ei0, E0, dcnt);
        scanA1<<<NBLK, 256, 0, s0>>>(dcnt, dbsum, N);
        scanC1<<<NBLK, 256, 0, s0>>>(dcnt, dbsum, drp, drp2, N);
        fill_one<<<(E0 + 255) / 256, 256, 0, s0>>>(ei0, E0, drp2, dcsr);
        gather_kernel<<<gather_blocks, 256, 0, s0>>>(embs, drp, dcsr, dagg, N);

        // ---- s0: layer-0 fused GEMM (needs weights) ----
        cudaStreamWaitEvent(s0, evW, 0);
        fused_tc<<<gemm_blocks, 512, SM_TOTAL, s0>>>(embs, dagg,
            dwh, dwl, dwh + DD * DD, dwl + DD * DD, b0, dx1, N, 1);

        // ---- s0: layer 1 (join layer-1 CSR, then gather1 + gemm1) ----
        cudaStreamWaitEvent(s0, evC, 0);
        gather_kernel<<<gather_blocks, 256, 0, s0>>>(dx1, drp + (NN + 1),
                                                     dcsr + NE, dagg, N);
        fused_tc<<<gemm_blocks, 512, SM_TOTAL, s0>>>(dx1, dagg,
            dwh + 2 * DD * DD, dwl + 2 * DD * DD,
            dwh + 3 * DD * DD, dwl + 3 * DD * DD, b1, out, N, 0);
    } else {
        // ---- serial fallback (same kernels, null stream) ----
        conv_w4<<<(4 * 4096 + 255) / 256, 256>>>(wl0, wr0, wl1, wr1, dwh, dwl);
        cudaMemsetAsync(dcnt, 0, 2 * NN * sizeof(int));
        count_one<<<(E0 + 255) / 256, 256>>>(ei0, E0, dcnt);
        count_one<<<(E1 + 255) / 256, 256>>>(ei1, E1, dcnt + NN);
        scanA1<<<NBLK, 256>>>(dcnt, dbsum, N);
        scanA1<<<NBLK, 256>>>(dcnt + NN, dbsum + NBLK, N);
        scanC1<<<NBLK, 256>>>(dcnt, dbsum, drp, drp2, N);
        scanC1<<<NBLK, 256>>>(dcnt + NN, dbsum + NBLK, drp + (NN + 1),
                              drp2 + NN, N);
        fill_one<<<(E0 + 255) / 256, 256>>>(ei0, E0, drp2, dcsr);
        fill_one<<<(E1 + 255) / 256, 256>>>(ei1, E1, drp2 + NN, dcsr + NE);

        gather_kernel<<<gather_blocks, 256>>>(embs, drp, dcsr, dagg, N);
        fused_tc<<<gemm_blocks, 512, SM_TOTAL>>>(embs, dagg,
            dwh, dwl, dwh + DD * DD, dwl + DD * DD, b0, dx1, N, 1);

        gather_kernel<<<gather_blocks, 256>>>(dx1, drp + (NN + 1), dcsr + NE,
                                              dagg, N);
        fused_tc<<<gemm_blocks, 512, SM_TOTAL>>>(dx1, dagg,
            dwh + 2 * DD * DD, dwl + 2 * DD * DD,
            dwh + 3 * DD * DD, dwl + 3 * DD * DD, b1, out, N, 0);
    }
}